// round 8
// baseline (speedup 1.0000x reference)
#include <cuda_runtime.h>
#include <math.h>

#define NC 23
#define NG 20000
#define NN 64
#define NH 64

#define BLKA 128
#define NBLKA ((NG + BLKA - 1) / BLKA)   // 157

#define SEGS 8
#define NTILES (SEGS * NC * NN)          // 11776
#define BLK 256
#define WARPS (BLK / 32)
#define STREAMS (WARPS * 2)              // 16 half-warp streams per block
#define GRIDMAIN (148 * 8)               // oversubscribed persistent grid

// ---- scratch (static device globals; no allocation in kernel_launch) ----
__device__ int          d_offset[NC + 1];
__device__ int          d_blockhist[NBLKA * NC];
__device__ int          d_assign[NG];
__device__ int          d_pack[NG];      // gene idx, bucketed by chromosome
__device__ float        d_outacc[NN * NC * NH];
__device__ float        d_sumw[NN * NC];
__device__ unsigned int d_ticket;

// ---------------- P1: per-gene assignment + per-block hist + zeroing -------

__global__ __launch_bounds__(BLKA)
void k_assign(const float* __restrict__ chrom) {
    __shared__ int s_hist[NC];
    const int tid = threadIdx.x;
    const int g = blockIdx.x * BLKA + tid;

    if (blockIdx.x == 0 && tid == 0) d_ticket = 0u;
    if (tid < NC) s_hist[tid] = 0;
    __syncthreads();

    if (g < NG) {
        int ci = 0;
        #pragma unroll
        for (int c = 0; c < NC; c++) {
            float v = chrom[c * NG + g];       // coalesced across g
            if (v != 0.f) ci = c;              // one-hot: exactly one hit
        }
        d_assign[g] = ci;
        atomicAdd(&s_hist[ci], 1);             // smem only
    }

    // fold accumulator zeroing in
    const int nt = NBLKA * BLKA;
    const int gt = blockIdx.x * BLKA + tid;
    for (int i = gt; i < NN * NC * NH; i += nt)
        d_outacc[i] = 0.f;
    if (gt < NN * NC)
        d_sumw[gt] = 0.f;

    __syncthreads();
    if (tid < NC) d_blockhist[blockIdx.x * NC + tid] = s_hist[tid];
}

// ---------------- P2: scatter; each block derives offsets locally ----------

__global__ __launch_bounds__(BLKA)
void k_scatter() {
    __shared__ int s_off[NC];    // exclusive global offset per chromosome
    __shared__ int s_base[NC];   // this block's running cursor per chromosome
    const int tid = threadIdx.x;
    const int bid = blockIdx.x;
    const int g = bid * BLKA + tid;

    // column totals + prefix of earlier blocks (23 threads, 157 ints each)
    int tot = 0, pre = 0;
    if (tid < NC) {
        #pragma unroll 4
        for (int b = 0; b < NBLKA; b++) {
            int h = d_blockhist[b * NC + tid];
            tot += h;
            if (b < bid) pre += h;
        }
    }
    // exclusive scan of tot over 23 lanes (warp 0)
    if (tid < 32) {
        int v = (tid < NC) ? tot : 0;
        int acc = v;
        #pragma unroll
        for (int d = 1; d < 32; d <<= 1) {
            int u = __shfl_up_sync(0xffffffffu, acc, d);
            if (tid >= d) acc += u;
        }
        if (tid < NC) {
            s_off[tid] = acc - v;
            if (bid == 0) {
                d_offset[tid] = acc - v;
                if (tid == NC - 1) d_offset[NC] = acc;
            }
        }
    }
    __syncthreads();
    if (tid < NC) s_base[tid] = s_off[tid] + pre;
    __syncthreads();

    if (g < NG) {
        int ci = d_assign[g];
        int pos = atomicAdd(&s_base[ci], 1);   // smem-only cursor
        d_pack[pos] = g;
    }
}

// ---------------- main fused pass -------------------------------------------
// Persistent-style grid; blocks pull (n,ci,seg) tiles from a global ticket.
// Per tile: 16 half-warp streams, 4-deep front-batched LDG.128 (.cs) pipeline.

__device__ __forceinline__ void compute_gene(
    const float4 xv, const float4 a4,
    unsigned hm, float4& acc, float& sumw)
{
    float s = a4.x * xv.x + a4.y * xv.y + a4.z * xv.z + a4.w * xv.w;
    s += __shfl_xor_sync(hm, s, 8);
    s += __shfl_xor_sync(hm, s, 4);
    s += __shfl_xor_sync(hm, s, 2);
    s += __shfl_xor_sync(hm, s, 1);
    float w = 0.f;
    if (s != 0.f) {
        float lr = s > 0.f ? s : 0.2f * s;   // leaky_relu(0.2)
        w = __expf(lr);
    }
    acc.x += w * xv.x;
    acc.y += w * xv.y;
    acc.z += w * xv.z;
    acc.w += w * xv.w;
    sumw += w;
}

__device__ __forceinline__ float4 ldcs4(const float* p) {
    return __ldcs(reinterpret_cast<const float4*>(p));
}

__global__ __launch_bounds__(BLK)
void k_main(const float* __restrict__ x, const float* __restrict__ attn) {
    const int tid  = threadIdx.x;
    const int wid  = tid >> 5;
    const int lane = tid & 31;
    const int hl   = lane & 15;   // lane within half-warp
    const int half = lane >> 4;
    const unsigned hm = half ? 0xffff0000u : 0x0000ffffu;
    const int stream = wid * 2 + half;
    const int step   = STREAMS;          // 16

    __shared__ float s_acc[NH];
    __shared__ float s_sum;
    __shared__ unsigned s_ticket;

    for (;;) {
        if (tid == 0) s_ticket = atomicAdd(&d_ticket, 1u);
        __syncthreads();
        const unsigned t = s_ticket;
        if (t >= NTILES) break;

        // decode: seg fastest, then ci, then n
        const int seg = t & (SEGS - 1);
        const int rem = t >> 3;              // SEGS == 8
        const int ci  = rem % NC;
        const int n   = rem / NC;

        const int bstart = d_offset[ci];
        const int bend   = d_offset[ci + 1];
        const int cnt    = bend - bstart;
        const int s0 = bstart + (int)((long long)cnt * seg / SEGS);
        const int s1 = bstart + (int)((long long)cnt * (seg + 1) / SEGS);

        const float4 a4 =
            *reinterpret_cast<const float4*>(attn + ci * NH + hl * 4);
        const float* xbase = x + (long long)n * NG * NH;

        float4 acc = make_float4(0.f, 0.f, 0.f, 0.f);
        float sumw = 0.f;

        int p = s0 + stream;

        // 4-way pipelined: 4 pack loads, 4 front-batched LDG.128, 4 chains
        for (; p + 3 * step < s1; p += 4 * step) {
            const int g0 = d_pack[p];
            const int g1 = d_pack[p + step];
            const int g2 = d_pack[p + 2 * step];
            const int g3 = d_pack[p + 3 * step];
            const float4 x0 = ldcs4(xbase + (long long)g0 * NH + hl * 4);
            const float4 x1 = ldcs4(xbase + (long long)g1 * NH + hl * 4);
            const float4 x2 = ldcs4(xbase + (long long)g2 * NH + hl * 4);
            const float4 x3 = ldcs4(xbase + (long long)g3 * NH + hl * 4);
            compute_gene(x0, a4, hm, acc, sumw);
            compute_gene(x1, a4, hm, acc, sumw);
            compute_gene(x2, a4, hm, acc, sumw);
            compute_gene(x3, a4, hm, acc, sumw);
        }
        for (; p < s1; p += step) {
            const int g = d_pack[p];
            const float4 xv = ldcs4(xbase + (long long)g * NH + hl * 4);
            compute_gene(xv, a4, hm, acc, sumw);
        }

        // combine halves: lanes 0..15 pick up lanes 16..31
        acc.x += __shfl_down_sync(0xffffffffu, acc.x, 16);
        acc.y += __shfl_down_sync(0xffffffffu, acc.y, 16);
        acc.z += __shfl_down_sync(0xffffffffu, acc.z, 16);
        acc.w += __shfl_down_sync(0xffffffffu, acc.w, 16);
        sumw  += __shfl_down_sync(0xffffffffu, sumw, 16);

        // block-level reduction in smem
        if (tid < NH) s_acc[tid] = 0.f;
        if (tid == 0) s_sum = 0.f;
        __syncthreads();

        if (lane < 16) {
            atomicAdd(&s_acc[hl * 4 + 0], acc.x);
            atomicAdd(&s_acc[hl * 4 + 1], acc.y);
            atomicAdd(&s_acc[hl * 4 + 2], acc.z);
            atomicAdd(&s_acc[hl * 4 + 3], acc.w);
        }
        if (lane == 0) atomicAdd(&s_sum, sumw);
        __syncthreads();

        const int slot = n * NC + ci;
        float* oacc = d_outacc + (long long)slot * NH;
        if (tid < NH) atomicAdd(&oacc[tid], s_acc[tid]);
        if (tid == 0) atomicAdd(&d_sumw[slot], s_sum);
        __syncthreads();   // protect s_acc/s_ticket reuse next iteration
    }
}

// ---------------- epilogue --------------------------------------------------

__global__ void k_final(float4* __restrict__ out) {
    int t = blockIdx.x * blockDim.x + threadIdx.x;   // float4 index
    if (t < NN * NC * NH / 4) {
        int ni = t / (NH / 4);
        float s = fmaxf(d_sumw[ni], 1e-10f);
        float4 v = reinterpret_cast<const float4*>(d_outacc)[t];
        v.x /= s; v.y /= s; v.z /= s; v.w /= s;
        out[t] = v;
    }
}

// ---------------- launcher --------------------------------------------------

extern "C" void kernel_launch(void* const* d_in, const int* in_sizes, int n_in,
                              void* d_out, int out_size) {
    const float* x     = (const float*)d_in[0];   // (N, G, H)
    const float* chrom = (const float*)d_in[1];   // (C, G)
    const float* attn  = (const float*)d_in[2];   // (C, H)
    float4* out = (float4*)d_out;                 // (N, C, H)

    (void)in_sizes; (void)n_in; (void)out_size;

    // bucket genes by chromosome (contention-free counting sort) + zero accum
    k_assign<<<NBLKA, BLKA>>>(chrom);
    k_scatter<<<NBLKA, BLKA>>>();

    // fused attention + weighted accumulation (dynamic tile scheduler)
    k_main<<<GRIDMAIN, BLK>>>(x, attn);

    // normalize
    const int nf4 = NN * NC * NH / 4;
    k_final<<<(nf4 + BLK - 1) / BLK, BLK>>>(out);
}

// round 9
// speedup vs baseline: 1.1784x; 1.1784x over previous
#include <cuda_runtime.h>
#include <math.h>

#define NC 23
#define NG 20000
#define NN 64
#define NH 64

#define BLKA 128
#define NBLKA ((NG + BLKA - 1) / BLKA)   // 157

#define SEGS 4
#define BLK 256
#define WARPS (BLK / 32)
#define STREAMS (WARPS * 2)              // 16 half-warp streams per block

// ---- scratch (static device globals; no allocation in kernel_launch) ----
__device__ int   d_offset[NC + 1];
__device__ int   d_blockhist[NBLKA * NC];
__device__ int   d_assign[NG];
__device__ int   d_pack[NG];             // gene idx, bucketed by chromosome
__device__ float d_outacc[NN * NC * NH];
__device__ float d_sumw[NN * NC];

// ---------------- P1: per-gene assignment + per-block hist + zeroing -------

__global__ __launch_bounds__(BLKA)
void k_assign(const float* __restrict__ chrom) {
    __shared__ int s_hist[NC];
    const int tid = threadIdx.x;
    const int g = blockIdx.x * BLKA + tid;

    if (tid < NC) s_hist[tid] = 0;
    __syncthreads();

    if (g < NG) {
        int ci = 0;
        #pragma unroll
        for (int c = 0; c < NC; c++) {
            float v = chrom[c * NG + g];       // coalesced across g
            if (v != 0.f) ci = c;              // one-hot: exactly one hit
        }
        d_assign[g] = ci;
        atomicAdd(&s_hist[ci], 1);             // smem only
    }

    // fold accumulator zeroing in
    const int nt = NBLKA * BLKA;
    const int gt = blockIdx.x * BLKA + tid;
    for (int i = gt; i < NN * NC * NH; i += nt)
        d_outacc[i] = 0.f;
    if (gt < NN * NC)
        d_sumw[gt] = 0.f;

    __syncthreads();
    if (tid < NC) d_blockhist[blockIdx.x * NC + tid] = s_hist[tid];
}

// ---------------- P2: scatter; each block derives offsets locally ----------

__global__ __launch_bounds__(BLKA)
void k_scatter() {
    __shared__ int s_off[NC];    // exclusive global offset per chromosome
    __shared__ int s_base[NC];   // this block's running cursor per chromosome
    const int tid = threadIdx.x;
    const int bid = blockIdx.x;
    const int g = bid * BLKA + tid;

    // column totals + prefix of earlier blocks (23 threads, 157 ints each)
    int tot = 0, pre = 0;
    if (tid < NC) {
        #pragma unroll 4
        for (int b = 0; b < NBLKA; b++) {
            int h = d_blockhist[b * NC + tid];
            tot += h;
            if (b < bid) pre += h;
        }
    }
    // exclusive scan of tot over 23 lanes (warp 0)
    if (tid < 32) {
        int v = (tid < NC) ? tot : 0;
        int acc = v;
        #pragma unroll
        for (int d = 1; d < 32; d <<= 1) {
            int u = __shfl_up_sync(0xffffffffu, acc, d);
            if (tid >= d) acc += u;
        }
        if (tid < NC) {
            s_off[tid] = acc - v;
            if (bid == 0) {
                d_offset[tid] = acc - v;
                if (tid == NC - 1) d_offset[NC] = acc;
            }
        }
    }
    __syncthreads();
    if (tid < NC) s_base[tid] = s_off[tid] + pre;
    __syncthreads();

    if (g < NG) {
        int ci = d_assign[g];
        int pos = atomicAdd(&s_base[ci], 1);   // smem-only cursor
        d_pack[pos] = g;
    }
}

// ---------------- main fused pass -------------------------------------------
// grid: (SEGS, NC, NN). Static partition (R3 structure). 4-deep front-batched
// LDG.128 pipeline per half-warp stream, with 2-stage gene-index prefetch so
// x-row loads never wait on the current iteration's pack loads.

__device__ __forceinline__ void compute_gene(
    const float4 xv, const float4 a4,
    unsigned hm, float4& acc, float& sumw)
{
    float s = a4.x * xv.x + a4.y * xv.y + a4.z * xv.z + a4.w * xv.w;
    s += __shfl_xor_sync(hm, s, 8);
    s += __shfl_xor_sync(hm, s, 4);
    s += __shfl_xor_sync(hm, s, 2);
    s += __shfl_xor_sync(hm, s, 1);
    float w = 0.f;
    if (s != 0.f) {
        float lr = s > 0.f ? s : 0.2f * s;   // leaky_relu(0.2)
        w = __expf(lr);
    }
    acc.x += w * xv.x;
    acc.y += w * xv.y;
    acc.z += w * xv.z;
    acc.w += w * xv.w;
    sumw += w;
}

__global__ __launch_bounds__(BLK)
void k_main(const float* __restrict__ x, const float* __restrict__ attn) {
    const int seg = blockIdx.x;
    const int ci  = blockIdx.y;
    const int n   = blockIdx.z;

    const int bstart = d_offset[ci];
    const int bend   = d_offset[ci + 1];
    const int cnt    = bend - bstart;
    const int s0 = bstart + (int)((long long)cnt * seg / SEGS);
    const int s1 = bstart + (int)((long long)cnt * (seg + 1) / SEGS);

    const int tid  = threadIdx.x;
    const int wid  = tid >> 5;
    const int lane = tid & 31;
    const int hl   = lane & 15;   // lane within half-warp
    const int half = lane >> 4;
    const unsigned hm = half ? 0xffff0000u : 0x0000ffffu;

    const float4 a4 =
        *reinterpret_cast<const float4*>(attn + ci * NH + hl * 4);

    const float* xbase = x + (long long)n * NG * NH;

    float4 acc = make_float4(0.f, 0.f, 0.f, 0.f);
    float sumw = 0.f;

    const int stream = wid * 2 + half;
    const int step   = STREAMS;          // 16

    int p = s0 + stream;

    // prefetch first group's indices
    int g0 = 0, g1 = 0, g2 = 0, g3 = 0;
    bool have = (p + 3 * step < s1);
    if (have) {
        g0 = d_pack[p];
        g1 = d_pack[p + step];
        g2 = d_pack[p + 2 * step];
        g3 = d_pack[p + 3 * step];
    }

    // steady state: issue x loads with already-resident indices, then load
    // next indices, then compute — pack latency hides under the compute chain
    while (have) {
        const float4 x0 = *reinterpret_cast<const float4*>(
            xbase + (long long)g0 * NH + hl * 4);
        const float4 x1 = *reinterpret_cast<const float4*>(
            xbase + (long long)g1 * NH + hl * 4);
        const float4 x2 = *reinterpret_cast<const float4*>(
            xbase + (long long)g2 * NH + hl * 4);
        const float4 x3 = *reinterpret_cast<const float4*>(
            xbase + (long long)g3 * NH + hl * 4);

        const int pn = p + 4 * step;
        have = (pn + 3 * step < s1);
        if (have) {
            g0 = d_pack[pn];
            g1 = d_pack[pn + step];
            g2 = d_pack[pn + 2 * step];
            g3 = d_pack[pn + 3 * step];
        }
        p = pn;

        compute_gene(x0, a4, hm, acc, sumw);
        compute_gene(x1, a4, hm, acc, sumw);
        compute_gene(x2, a4, hm, acc, sumw);
        compute_gene(x3, a4, hm, acc, sumw);
    }
    for (; p < s1; p += step) {
        const int g = d_pack[p];
        const float4 xv = *reinterpret_cast<const float4*>(
            xbase + (long long)g * NH + hl * 4);
        compute_gene(xv, a4, hm, acc, sumw);
    }

    // combine halves: lanes 0..15 pick up lanes 16..31
    acc.x += __shfl_down_sync(0xffffffffu, acc.x, 16);
    acc.y += __shfl_down_sync(0xffffffffu, acc.y, 16);
    acc.z += __shfl_down_sync(0xffffffffu, acc.z, 16);
    acc.w += __shfl_down_sync(0xffffffffu, acc.w, 16);
    sumw  += __shfl_down_sync(0xffffffffu, sumw, 16);

    // block-level reduction in smem
    __shared__ float s_acc[NH];
    __shared__ float s_sum;
    if (tid < NH) s_acc[tid] = 0.f;
    if (tid == 0) s_sum = 0.f;
    __syncthreads();

    if (lane < 16) {
        atomicAdd(&s_acc[hl * 4 + 0], acc.x);
        atomicAdd(&s_acc[hl * 4 + 1], acc.y);
        atomicAdd(&s_acc[hl * 4 + 2], acc.z);
        atomicAdd(&s_acc[hl * 4 + 3], acc.w);
    }
    if (lane == 0) atomicAdd(&s_sum, sumw);
    __syncthreads();

    const int slot = n * NC + ci;
    float* oacc = d_outacc + (long long)slot * NH;
    if (tid < NH) atomicAdd(&oacc[tid], s_acc[tid]);
    if (tid == 0) atomicAdd(&d_sumw[slot], s_sum);
}

// ---------------- epilogue --------------------------------------------------

__global__ void k_final(float4* __restrict__ out) {
    int t = blockIdx.x * blockDim.x + threadIdx.x;   // float4 index
    if (t < NN * NC * NH / 4) {
        int ni = t / (NH / 4);
        float s = fmaxf(d_sumw[ni], 1e-10f);
        float4 v = reinterpret_cast<const float4*>(d_outacc)[t];
        v.x /= s; v.y /= s; v.z /= s; v.w /= s;
        out[t] = v;
    }
}

// ---------------- launcher --------------------------------------------------

extern "C" void kernel_launch(void* const* d_in, const int* in_sizes, int n_in,
                              void* d_out, int out_size) {
    const float* x     = (const float*)d_in[0];   // (N, G, H)
    const float* chrom = (const float*)d_in[1];   // (C, G)
    const float* attn  = (const float*)d_in[2];   // (C, H)
    float4* out = (float4*)d_out;                 // (N, C, H)

    (void)in_sizes; (void)n_in; (void)out_size;

    // bucket genes by chromosome (contention-free counting sort) + zero accum
    k_assign<<<NBLKA, BLKA>>>(chrom);
    k_scatter<<<NBLKA, BLKA>>>();

    // fused attention + weighted accumulation (single pass over x)
    dim3 grid(SEGS, NC, NN);
    k_main<<<grid, BLK>>>(x, attn);

    // normalize
    const int nf4 = NN * NC * NH / 4;
    k_final<<<(nf4 + BLK - 1) / BLK, BLK>>>(out);
}